// round 1
// baseline (speedup 1.0000x reference)
#include <cuda_runtime.h>
#include <cuda_bf16.h>
#include <cstdint>
#include <cmath>

// Problem constants
#define BATCH 8
#define CH    512
#define NTOK  4096      // 64*64
#define NH    16
#define HD    32

// ---------------- scratch (device globals; allocation-free) ----------------
__device__ float g_Yq[BATCH * CH * NTOK];
__device__ float g_Yk[BATCH * CH * NTOK];
__device__ float g_Yv[BATCH * CH * NTOK];
__device__ float g_M [BATCH * CH * NTOK];
__device__ float g_Ksum[BATCH * CH];

// ---------------- helpers ----------------
__device__ __forceinline__ float to_tf32(float x) {
    uint32_t u;
    asm("cvt.rna.tf32.f32 %0, %1;" : "=r"(u) : "f"(x));
    return __uint_as_float(u);
}

__device__ __forceinline__ void mma_tf32(float c[4], const uint32_t a[4], const uint32_t b[2]) {
    asm volatile(
        "mma.sync.aligned.m16n8k8.row.col.f32.tf32.tf32.f32 "
        "{%0,%1,%2,%3}, {%4,%5,%6,%7}, {%8,%9}, {%0,%1,%2,%3};"
        : "+f"(c[0]), "+f"(c[1]), "+f"(c[2]), "+f"(c[3])
        : "r"(a[0]), "r"(a[1]), "r"(a[2]), "r"(a[3]),
          "r"(b[0]), "r"(b[1]));
}

// =====================================================================
// GEMM: C[b, d, n] = sum_c A[d, c] * B[b, c, n]  (+ bias[d])
// A: [512,512] row-major.  B, C: [8][512][4096].
// BM=128, BN=128, BK=16, 256 threads (8 warps: 4 along M x 2 along N),
// warp tile 32x64, tf32 mma.sync m16n8k8, double-buffered smem.
// =====================================================================
#define GBM 128
#define GBN 128
#define GBK 16
#define APAD 4

__global__ __launch_bounds__(256) void gemm_tf32(
    const float* __restrict__ A,
    const float* __restrict__ B,
    float* __restrict__ C,
    const float* __restrict__ bias)
{
    __shared__ float As[2][GBK][GBM + APAD];
    __shared__ float Bs[2][GBK][GBN + APAD];

    const int b  = blockIdx.z;
    const int m0 = blockIdx.y * GBM;
    const int n0 = blockIdx.x * GBN;
    const float* Bb = B + (size_t)b * CH * NTOK;
    float*       Cb = C + (size_t)b * CH * NTOK;

    const int tid  = threadIdx.x;
    const int lane = tid & 31;
    const int wid  = tid >> 5;
    const int wm   = wid & 3;      // warp row 0..3
    const int wn   = wid >> 2;     // warp col 0..1
    const int gr   = lane >> 2;    // 0..7
    const int kc   = lane & 3;     // 0..3

    // A tile load mapping: 128 rows x 16 cols, 8 floats per thread
    const int ar = tid >> 1;            // 0..127
    const int ac = (tid & 1) * 8;       // 0 or 8
    // B tile load mapping: 16 rows x 128 cols
    const int br = tid >> 5;            // 0..7
    const int bc = (tid & 31) * 4;

    float acc[2][8][4];
#pragma unroll
    for (int i = 0; i < 2; i++)
#pragma unroll
        for (int j = 0; j < 8; j++)
#pragma unroll
            for (int r = 0; r < 4; r++) acc[i][j][r] = 0.f;

    float4 ra0, ra1, rb0, rb1;
    // preload tile 0
    {
        const float* Ap = A + (size_t)(m0 + ar) * CH + ac;
        ra0 = *(const float4*)(Ap);
        ra1 = *(const float4*)(Ap + 4);
        const float* Bp = Bb + (size_t)br * NTOK + n0 + bc;
        rb0 = *(const float4*)(Bp);
        rb1 = *(const float4*)(Bp + (size_t)8 * NTOK);
    }
    // store tile 0
    {
        const float* fa0 = (const float*)&ra0;
        const float* fa1 = (const float*)&ra1;
#pragma unroll
        for (int u = 0; u < 4; u++) {
            As[0][ac + u][ar]     = to_tf32(fa0[u]);
            As[0][ac + 4 + u][ar] = to_tf32(fa1[u]);
        }
        float4 t0 = make_float4(to_tf32(rb0.x), to_tf32(rb0.y), to_tf32(rb0.z), to_tf32(rb0.w));
        float4 t1 = make_float4(to_tf32(rb1.x), to_tf32(rb1.y), to_tf32(rb1.z), to_tf32(rb1.w));
        *(float4*)&Bs[0][br][bc]     = t0;
        *(float4*)&Bs[0][br + 8][bc] = t1;
    }
    __syncthreads();

    const int KT = CH / GBK;  // 32
    int cur = 0;
#pragma unroll 1
    for (int kt = 0; kt < KT; ++kt) {
        if (kt + 1 < KT) {
            const float* Ap = A + (size_t)(m0 + ar) * CH + (kt + 1) * GBK + ac;
            ra0 = *(const float4*)(Ap);
            ra1 = *(const float4*)(Ap + 4);
            const float* Bp = Bb + (size_t)((kt + 1) * GBK + br) * NTOK + n0 + bc;
            rb0 = *(const float4*)(Bp);
            rb1 = *(const float4*)(Bp + (size_t)8 * NTOK);
        }

#pragma unroll
        for (int ks = 0; ks < 2; ++ks) {
            const int k0 = ks * 8;
            uint32_t af[2][4];
            uint32_t bf[8][2];
#pragma unroll
            for (int i = 0; i < 2; i++) {
                const int rm = wm * 32 + i * 16;
                af[i][0] = __float_as_uint(As[cur][k0 + kc][rm + gr]);
                af[i][1] = __float_as_uint(As[cur][k0 + kc][rm + gr + 8]);
                af[i][2] = __float_as_uint(As[cur][k0 + kc + 4][rm + gr]);
                af[i][3] = __float_as_uint(As[cur][k0 + kc + 4][rm + gr + 8]);
            }
#pragma unroll
            for (int j = 0; j < 8; j++) {
                const int cn = wn * 64 + j * 8;
                bf[j][0] = __float_as_uint(Bs[cur][k0 + kc][cn + gr]);
                bf[j][1] = __float_as_uint(Bs[cur][k0 + kc + 4][cn + gr]);
            }
#pragma unroll
            for (int i = 0; i < 2; i++)
#pragma unroll
                for (int j = 0; j < 8; j++)
                    mma_tf32(acc[i][j], af[i], bf[j]);
        }

        if (kt + 1 < KT) {
            const int nxt = cur ^ 1;
            const float* fa0 = (const float*)&ra0;
            const float* fa1 = (const float*)&ra1;
#pragma unroll
            for (int u = 0; u < 4; u++) {
                As[nxt][ac + u][ar]     = to_tf32(fa0[u]);
                As[nxt][ac + 4 + u][ar] = to_tf32(fa1[u]);
            }
            float4 t0 = make_float4(to_tf32(rb0.x), to_tf32(rb0.y), to_tf32(rb0.z), to_tf32(rb0.w));
            float4 t1 = make_float4(to_tf32(rb1.x), to_tf32(rb1.y), to_tf32(rb1.z), to_tf32(rb1.w));
            *(float4*)&Bs[nxt][br][bc]     = t0;
            *(float4*)&Bs[nxt][br + 8][bc] = t1;
        }
        __syncthreads();
        cur ^= 1;
    }

    // epilogue
#pragma unroll
    for (int i = 0; i < 2; i++) {
        const int row = m0 + wm * 32 + i * 16 + gr;
        const float bi0 = bias ? bias[row] : 0.f;
        const float bi1 = bias ? bias[row + 8] : 0.f;
#pragma unroll
        for (int j = 0; j < 8; j++) {
            const int col = n0 + wn * 64 + j * 8 + kc * 2;
            float2 v0 = make_float2(acc[i][j][0] + bi0, acc[i][j][1] + bi0);
            float2 v1 = make_float2(acc[i][j][2] + bi1, acc[i][j][3] + bi1);
            *(float2*)&Cb[(size_t)row * NTOK + col]       = v0;
            *(float2*)&Cb[(size_t)(row + 8) * NTOK + col] = v1;
        }
    }
}

// =====================================================================
// Ksum[b, c] = sum_n (elu(Yk[b,c,n]) + 1)
// one block per (b,c) row
// =====================================================================
__global__ __launch_bounds__(256) void ksum_kernel()
{
    const int row = blockIdx.x;  // b*512 + c
    const float* p = g_Yk + (size_t)row * NTOK;
    float s = 0.f;
    for (int n = threadIdx.x; n < NTOK; n += 256) {
        const float x = p[n];
        s += (x > 0.f) ? (x + 1.f) : expf(x);
    }
    __shared__ float red[256];
    red[threadIdx.x] = s;
    __syncthreads();
    for (int st = 128; st > 0; st >>= 1) {
        if (threadIdx.x < st) red[threadIdx.x] += red[threadIdx.x + st];
        __syncthreads();
    }
    if (threadIdx.x == 0) g_Ksum[row] = red[0];
}

// =====================================================================
// Middle stage. Per token:
//   S[h,h'] = sum_d Q[h,d] K[h',d]        (Q,K = elu(Y)+1)
//   Z[h]    = 1 / (sum_d Q[h,d]*Ksum[h,d] + eps)
//   O[h,m]  = Z[h] * sum_h' S[h,h'] V[h',m]
// M[b, h*32+m, n] = O[h,m]
// Block: 128 threads (4 warps), TN=8 tokens, 2 tokens per warp.
// =====================================================================
#define TN   8
#define TOKP 529   // per-token matrix: 16 heads * 33 (padded) + 1
#define SSTR 273   // per-token S: 16*17 + 1

__global__ __launch_bounds__(128) void mid_kernel()
{
    __shared__ float buf0[TN * TOKP];  // K, later O staging
    __shared__ float buf1[TN * TOKP];  // Q, later V
    __shared__ float Ss[TN * SSTR];
    __shared__ float Zs[TN * 17];
    __shared__ float Ksm[16 * 33];

    const int blk = blockIdx.x;      // BATCH * (NTOK/TN) = 8*512
    const int b   = blk >> 9;
    const int n0  = (blk & 511) * TN;
    const size_t base = (size_t)b * CH * NTOK + n0;
    const int tid = threadIdx.x;

    for (int i = tid; i < CH; i += 128)
        Ksm[(i >> 5) * 33 + (i & 31)] = g_Ksum[b * CH + i];

    // load K (elu+1) -> buf0, Q (elu+1) -> buf1
    for (int i = tid; i < CH * TN; i += 128) {
        const int tn = i & (TN - 1);
        const int c  = i >> 3;
        const float xk = g_Yk[base + (size_t)c * NTOK + tn];
        const float xq = g_Yq[base + (size_t)c * NTOK + tn];
        const int off = tn * TOKP + (c >> 5) * 33 + (c & 31);
        buf0[off] = (xk > 0.f) ? (xk + 1.f) : expf(xk);
        buf1[off] = (xq > 0.f) ? (xq + 1.f) : expf(xq);
    }
    __syncthreads();

    const int w    = tid >> 5;
    const int lane = tid & 31;
    const int hp   = lane & 15;
    const int half = lane >> 4;

    // Phase A: S and Z
#pragma unroll
    for (int tt = 0; tt < 2; ++tt) {
        const int t = w * 2 + tt;
        const float* Kt = &buf0[t * TOKP];
        const float* Qt = &buf1[t * TOKP];
        float kcol[32];
#pragma unroll
        for (int d = 0; d < 32; d++) kcol[d] = Kt[hp * 33 + d];
#pragma unroll
        for (int hi = 0; hi < 8; hi++) {
            const int h = half * 8 + hi;
            float s = 0.f;
#pragma unroll
            for (int d = 0; d < 32; d++) s = fmaf(Qt[h * 33 + d], kcol[d], s);
            Ss[t * SSTR + h * 17 + hp] = s;
        }
        if (half == 0) {
            float dn = 0.f;
#pragma unroll
            for (int d = 0; d < 32; d++) dn = fmaf(Qt[hp * 33 + d], Ksm[hp * 33 + d], dn);
            Zs[t * 17 + hp] = 1.f / (dn + 1e-5f);
        }
    }
    __syncthreads();

    // load V -> buf1 (overwrites Q)
    for (int i = tid; i < CH * TN; i += 128) {
        const int tn = i & (TN - 1);
        const int c  = i >> 3;
        buf1[tn * TOKP + (c >> 5) * 33 + (c & 31)] = g_Yv[base + (size_t)c * NTOK + tn];
    }
    __syncthreads();

    // Phase B: O = diag(Z) * S * V   -> buf0 (overwrites K)
#pragma unroll
    for (int tt = 0; tt < 2; ++tt) {
        const int t = w * 2 + tt;
        const float* Vt = &buf1[t * TOKP];
        float vcol[16];
#pragma unroll
        for (int h = 0; h < 16; h++) vcol[h] = Vt[h * 33 + lane];
#pragma unroll
        for (int h = 0; h < 16; h++) {
            float a = 0.f;
#pragma unroll
            for (int q = 0; q < 16; q++) a = fmaf(Ss[t * SSTR + h * 17 + q], vcol[q], a);
            buf0[t * TOKP + h * 33 + lane] = a * Zs[t * 17 + h];
        }
    }
    __syncthreads();

    // write out M (coalesced)
    for (int i = tid; i < CH * TN; i += 128) {
        const int tn = i & (TN - 1);
        const int c  = i >> 3;
        g_M[base + (size_t)c * NTOK + tn] = buf0[tn * TOKP + (c >> 5) * 33 + (c & 31)];
    }
}

// =====================================================================
extern "C" void kernel_launch(void* const* d_in, const int* in_sizes, int n_in,
                              void* d_out, int out_size)
{
    (void)in_sizes; (void)n_in; (void)out_size;
    const float* q  = (const float*)d_in[0];
    const float* k  = (const float*)d_in[1];
    const float* v  = (const float*)d_in[2];
    const float* Wq = (const float*)d_in[3];
    const float* Wk = (const float*)d_in[4];
    const float* Wv = (const float*)d_in[5];
    const float* Wp = (const float*)d_in[6];
    const float* bp = (const float*)d_in[7];
    float* out = (float*)d_out;

    float *Yq, *Yk, *Yv, *M;
    cudaGetSymbolAddress((void**)&Yq, g_Yq);
    cudaGetSymbolAddress((void**)&Yk, g_Yk);
    cudaGetSymbolAddress((void**)&Yv, g_Yv);
    cudaGetSymbolAddress((void**)&M,  g_M);

    dim3 gg(NTOK / GBN, CH / GBM, BATCH);  // (32, 4, 8)
    gemm_tf32<<<gg, 256>>>(Wq, q, Yq, nullptr);
    gemm_tf32<<<gg, 256>>>(Wk, k, Yk, nullptr);
    gemm_tf32<<<gg, 256>>>(Wv, v, Yv, nullptr);
    ksum_kernel<<<BATCH * CH, 256>>>();
    mid_kernel<<<BATCH * (NTOK / TN), 128>>>();
    gemm_tf32<<<gg, 256>>>(Wp, M, out, bp);
}

// round 2
// speedup vs baseline: 1.5312x; 1.5312x over previous
#include <cuda_runtime.h>
#include <cuda_bf16.h>
#include <cstdint>
#include <cmath>

#define BATCH 8
#define CH    512
#define NTOK  4096
#define NH    16
#define HD    32

// ---------------- scratch (device globals) ----------------
__device__ __nv_bfloat16 g_Q[BATCH * CH * NTOK];
__device__ __nv_bfloat16 g_K[BATCH * CH * NTOK];
__device__ __nv_bfloat16 g_V[BATCH * CH * NTOK];
__device__ __nv_bfloat16 g_M[BATCH * CH * NTOK];
__device__ float g_Ksum[BATCH * CH];

// ---------------- mma / ldmatrix helpers ----------------
__device__ __forceinline__ void mma_bf16(float c[4], const uint32_t a[4], const uint32_t b[2]) {
    asm volatile(
        "mma.sync.aligned.m16n8k16.row.col.f32.bf16.bf16.f32 "
        "{%0,%1,%2,%3}, {%4,%5,%6,%7}, {%8,%9}, {%0,%1,%2,%3};"
        : "+f"(c[0]), "+f"(c[1]), "+f"(c[2]), "+f"(c[3])
        : "r"(a[0]), "r"(a[1]), "r"(a[2]), "r"(a[3]),
          "r"(b[0]), "r"(b[1]));
}

__device__ __forceinline__ void ldsm_x4(uint32_t r[4], uint32_t addr) {
    asm volatile("ldmatrix.sync.aligned.m8n8.x4.shared.b16 {%0,%1,%2,%3}, [%4];"
                 : "=r"(r[0]), "=r"(r[1]), "=r"(r[2]), "=r"(r[3]) : "r"(addr));
}
__device__ __forceinline__ void ldsm_x4_t(uint32_t r[4], uint32_t addr) {
    asm volatile("ldmatrix.sync.aligned.m8n8.x4.trans.shared.b16 {%0,%1,%2,%3}, [%4];"
                 : "=r"(r[0]), "=r"(r[1]), "=r"(r[2]), "=r"(r[3]) : "r"(addr));
}

struct Pack16 { uint4 u0, u1; };  // 16 bf16

// =====================================================================
// GEMM: C[b,d,n] = sum_c A[d,c] * B[b,c,n] (+bias, +elu+1)
// A fp32 [512,512] row-major; B [8][512][4096] (fp32 or bf16);
// C [8][512][4096] (bf16 or fp32).
// BM=128 BN=128 BK=32, 256 thr (8 warps 4x2), warp tile 32x64,
// bf16 mma m16n8k16 + ldmatrix, double-buffered smem.
// =====================================================================
#define GBM 128
#define GBN 128
#define GBK 32
#define SA  40    // As row stride in bf16 (128 rows x 32 k)
#define SB  136   // Bs row stride in bf16 (32 rows x 128 n)

template<typename InT, typename OutT, bool ELU, bool BIAS>
__global__ __launch_bounds__(256) void gemm_bf16(
    const float* __restrict__ A,
    const InT*  __restrict__ B,
    OutT*       __restrict__ C,
    const float* __restrict__ bias)
{
    __shared__ __nv_bfloat16 As[2][GBM * SA];
    __shared__ __nv_bfloat16 Bs[2][GBK * SB];

    const int b  = blockIdx.z;
    const int m0 = blockIdx.y * GBM;
    const int n0 = blockIdx.x * GBN;
    const InT* Bb = B + (size_t)b * CH * NTOK;
    OutT*      Cb = C + (size_t)b * CH * NTOK;

    const int tid  = threadIdx.x;
    const int lane = tid & 31;
    const int wid  = tid >> 5;
    const int wm   = wid & 3;
    const int wn   = wid >> 2;
    const int gr   = lane >> 2;
    const int kc   = lane & 3;

    // global load mapping
    const int am = tid >> 1;            // A row 0..127
    const int ak = (tid & 1) * 16;      // A k-half
    const int bc = tid >> 3;            // B k-row 0..31
    const int bn = (tid & 7) * 16;      // B n offset

    // ldmatrix per-lane offsets (bf16 element units)
    const int a_lrow = lane & 15;
    const int a_lc8  = (lane >> 4) * 8;
    const int b_lrow = ((lane >> 3) & 1) * 8 + (lane & 7);
    const int b_lc8  = (lane >> 4) * 8;

    const uint32_t As_sh = (uint32_t)__cvta_generic_to_shared(&As[0][0]);
    const uint32_t Bs_sh = (uint32_t)__cvta_generic_to_shared(&Bs[0][0]);

    float acc[2][8][4];
#pragma unroll
    for (int i = 0; i < 2; i++)
#pragma unroll
        for (int j = 0; j < 8; j++)
#pragma unroll
            for (int r = 0; r < 4; r++) acc[i][j][r] = 0.f;

    auto loadA = [&](int kt) -> Pack16 {
        const float* p = A + (size_t)(m0 + am) * CH + kt * GBK + ak;
        float4 f0 = *(const float4*)(p);
        float4 f1 = *(const float4*)(p + 4);
        float4 f2 = *(const float4*)(p + 8);
        float4 f3 = *(const float4*)(p + 12);
        union { __nv_bfloat162 h[8]; Pack16 pk; } z;
        z.h[0] = __float22bfloat162_rn(make_float2(f0.x, f0.y));
        z.h[1] = __float22bfloat162_rn(make_float2(f0.z, f0.w));
        z.h[2] = __float22bfloat162_rn(make_float2(f1.x, f1.y));
        z.h[3] = __float22bfloat162_rn(make_float2(f1.z, f1.w));
        z.h[4] = __float22bfloat162_rn(make_float2(f2.x, f2.y));
        z.h[5] = __float22bfloat162_rn(make_float2(f2.z, f2.w));
        z.h[6] = __float22bfloat162_rn(make_float2(f3.x, f3.y));
        z.h[7] = __float22bfloat162_rn(make_float2(f3.z, f3.w));
        return z.pk;
    };
    auto loadB = [&](int kt) -> Pack16 {
        const InT* p = Bb + (size_t)(kt * GBK + bc) * NTOK + n0 + bn;
        if constexpr (sizeof(InT) == 4) {
            float4 f0 = *(const float4*)(p);
            float4 f1 = *(const float4*)(p + 4);
            float4 f2 = *(const float4*)(p + 8);
            float4 f3 = *(const float4*)(p + 12);
            union { __nv_bfloat162 h[8]; Pack16 pk; } z;
            z.h[0] = __float22bfloat162_rn(make_float2(f0.x, f0.y));
            z.h[1] = __float22bfloat162_rn(make_float2(f0.z, f0.w));
            z.h[2] = __float22bfloat162_rn(make_float2(f1.x, f1.y));
            z.h[3] = __float22bfloat162_rn(make_float2(f1.z, f1.w));
            z.h[4] = __float22bfloat162_rn(make_float2(f2.x, f2.y));
            z.h[5] = __float22bfloat162_rn(make_float2(f2.z, f2.w));
            z.h[6] = __float22bfloat162_rn(make_float2(f3.x, f3.y));
            z.h[7] = __float22bfloat162_rn(make_float2(f3.z, f3.w));
            return z.pk;
        } else {
            Pack16 pk;
            pk.u0 = *(const uint4*)(p);
            pk.u1 = *(const uint4*)(p + 8);
            return pk;
        }
    };
    auto storeA = [&](int buf, Pack16 pk) {
        __nv_bfloat16* d = &As[buf][am * SA + ak];
        *(uint4*)(d)     = pk.u0;
        *(uint4*)(d + 8) = pk.u1;
    };
    auto storeB = [&](int buf, Pack16 pk) {
        __nv_bfloat16* d = &Bs[buf][bc * SB + bn];
        *(uint4*)(d)     = pk.u0;
        *(uint4*)(d + 8) = pk.u1;
    };

    {
        Pack16 pa = loadA(0);
        Pack16 pb = loadB(0);
        storeA(0, pa);
        storeB(0, pb);
    }
    __syncthreads();

    const int KT = CH / GBK;  // 16
    int cur = 0;
#pragma unroll 1
    for (int kt = 0; kt < KT; ++kt) {
        Pack16 pa, pb;
        if (kt + 1 < KT) {
            pa = loadA(kt + 1);
            pb = loadB(kt + 1);
        }

#pragma unroll
        for (int ks = 0; ks < 2; ++ks) {
            const int k0 = ks * 16;
            uint32_t af[2][4];
            uint32_t bf[8][2];
#pragma unroll
            for (int i = 0; i < 2; i++) {
                uint32_t addr = As_sh +
                    (uint32_t)((cur * GBM * SA +
                                (wm * 32 + i * 16 + a_lrow) * SA + k0 + a_lc8) * 2);
                ldsm_x4(af[i], addr);
            }
#pragma unroll
            for (int jj = 0; jj < 4; jj++) {
                uint32_t r[4];
                uint32_t addr = Bs_sh +
                    (uint32_t)((cur * GBK * SB + (k0 + b_lrow) * SB +
                                wn * 64 + jj * 16 + b_lc8) * 2);
                ldsm_x4_t(r, addr);
                bf[jj * 2][0]     = r[0];
                bf[jj * 2][1]     = r[1];
                bf[jj * 2 + 1][0] = r[2];
                bf[jj * 2 + 1][1] = r[3];
            }
#pragma unroll
            for (int i = 0; i < 2; i++)
#pragma unroll
                for (int j = 0; j < 8; j++)
                    mma_bf16(acc[i][j], af[i], bf[j]);
        }

        if (kt + 1 < KT) {
            storeA(cur ^ 1, pa);
            storeB(cur ^ 1, pb);
        }
        __syncthreads();
        cur ^= 1;
    }

    // epilogue
#pragma unroll
    for (int i = 0; i < 2; i++) {
        const int row = m0 + wm * 32 + i * 16 + gr;
        const float bi0 = BIAS ? bias[row] : 0.f;
        const float bi1 = BIAS ? bias[row + 8] : 0.f;
#pragma unroll
        for (int j = 0; j < 8; j++) {
            const int col = n0 + wn * 64 + j * 8 + kc * 2;
            float c0 = acc[i][j][0], c1 = acc[i][j][1];
            float c2 = acc[i][j][2], c3 = acc[i][j][3];
            if (ELU) {
                c0 = (c0 > 0.f) ? (c0 + 1.f) : __expf(c0);
                c1 = (c1 > 0.f) ? (c1 + 1.f) : __expf(c1);
                c2 = (c2 > 0.f) ? (c2 + 1.f) : __expf(c2);
                c3 = (c3 > 0.f) ? (c3 + 1.f) : __expf(c3);
            }
            if (BIAS) { c0 += bi0; c1 += bi0; c2 += bi1; c3 += bi1; }
            if constexpr (sizeof(OutT) == 2) {
                *(__nv_bfloat162*)&Cb[(size_t)row * NTOK + col] =
                    __float22bfloat162_rn(make_float2(c0, c1));
                *(__nv_bfloat162*)&Cb[(size_t)(row + 8) * NTOK + col] =
                    __float22bfloat162_rn(make_float2(c2, c3));
            } else {
                *(float2*)&Cb[(size_t)row * NTOK + col]       = make_float2(c0, c1);
                *(float2*)&Cb[(size_t)(row + 8) * NTOK + col] = make_float2(c2, c3);
            }
        }
    }
}

// =====================================================================
// Ksum[b,c] = sum_n K[b,c,n]   (K already elu+1'd, bf16)
// =====================================================================
__global__ __launch_bounds__(256) void ksum_kernel()
{
    const int row = blockIdx.x;
    const __nv_bfloat16* p = g_K + (size_t)row * NTOK;
    const int i = threadIdx.x * 16;
    uint4 u0 = *(const uint4*)(p + i);
    uint4 u1 = *(const uint4*)(p + i + 8);
    float s = 0.f;
    const __nv_bfloat162* h0 = (const __nv_bfloat162*)&u0;
    const __nv_bfloat162* h1 = (const __nv_bfloat162*)&u1;
#pragma unroll
    for (int j = 0; j < 4; j++) {
        float2 f0 = __bfloat1622float2(h0[j]);
        float2 f1 = __bfloat1622float2(h1[j]);
        s += f0.x + f0.y + f1.x + f1.y;
    }
#pragma unroll
    for (int o = 16; o > 0; o >>= 1) s += __shfl_xor_sync(0xffffffffu, s, o);
    __shared__ float red[8];
    if ((threadIdx.x & 31) == 0) red[threadIdx.x >> 5] = s;
    __syncthreads();
    if (threadIdx.x == 0) {
        float t = 0.f;
#pragma unroll
        for (int w = 0; w < 8; w++) t += red[w];
        g_Ksum[row] = t;
    }
}

// =====================================================================
// Middle stage (per token, fp32 math in smem):
//   S = Q K^T (16x16, d=32);  Z[h] = 1/(Q[h]·Ksum[h] + eps)
//   O = diag(Z) S V           -> g_M (bf16)
// =====================================================================
#define TN   8
#define TOKP 529
#define SSTR 273

__global__ __launch_bounds__(128) void mid_kernel()
{
    __shared__ float buf0[TN * TOKP];
    __shared__ float buf1[TN * TOKP];
    __shared__ float Ss[TN * SSTR];
    __shared__ float Zs[TN * 17];
    __shared__ float Ksm[16 * 33];

    const int blk = blockIdx.x;
    const int b   = blk >> 9;
    const int n0  = (blk & 511) * TN;
    const size_t base = (size_t)b * CH * NTOK + n0;
    const int tid = threadIdx.x;

    for (int i = tid; i < CH; i += 128)
        Ksm[(i >> 5) * 33 + (i & 31)] = g_Ksum[b * CH + i];

    for (int i = tid; i < CH * TN; i += 128) {
        const int tn = i & (TN - 1);
        const int c  = i >> 3;
        const int off = tn * TOKP + (c >> 5) * 33 + (c & 31);
        buf0[off] = __bfloat162float(g_K[base + (size_t)c * NTOK + tn]);
        buf1[off] = __bfloat162float(g_Q[base + (size_t)c * NTOK + tn]);
    }
    __syncthreads();

    const int w    = tid >> 5;
    const int lane = tid & 31;
    const int hp   = lane & 15;
    const int half = lane >> 4;

#pragma unroll
    for (int tt = 0; tt < 2; ++tt) {
        const int t = w * 2 + tt;
        const float* Kt = &buf0[t * TOKP];
        const float* Qt = &buf1[t * TOKP];
        float kcol[32];
#pragma unroll
        for (int d = 0; d < 32; d++) kcol[d] = Kt[hp * 33 + d];
#pragma unroll
        for (int hi = 0; hi < 8; hi++) {
            const int h = half * 8 + hi;
            float s = 0.f;
#pragma unroll
            for (int d = 0; d < 32; d++) s = fmaf(Qt[h * 33 + d], kcol[d], s);
            Ss[t * SSTR + h * 17 + hp] = s;
        }
        if (half == 0) {
            float dn = 0.f;
#pragma unroll
            for (int d = 0; d < 32; d++) dn = fmaf(Qt[hp * 33 + d], Ksm[hp * 33 + d], dn);
            Zs[t * 17 + hp] = 1.f / (dn + 1e-5f);
        }
    }
    __syncthreads();

    for (int i = tid; i < CH * TN; i += 128) {
        const int tn = i & (TN - 1);
        const int c  = i >> 3;
        buf1[tn * TOKP + (c >> 5) * 33 + (c & 31)] =
            __bfloat162float(g_V[base + (size_t)c * NTOK + tn]);
    }
    __syncthreads();

#pragma unroll
    for (int tt = 0; tt < 2; ++tt) {
        const int t = w * 2 + tt;
        const float* Vt = &buf1[t * TOKP];
        float vcol[16];
#pragma unroll
        for (int h = 0; h < 16; h++) vcol[h] = Vt[h * 33 + lane];
#pragma unroll
        for (int h = 0; h < 16; h++) {
            float a = 0.f;
#pragma unroll
            for (int q = 0; q < 16; q++) a = fmaf(Ss[t * SSTR + h * 17 + q], vcol[q], a);
            buf0[t * TOKP + h * 33 + lane] = a * Zs[t * 17 + h];
        }
    }
    __syncthreads();

    for (int i = tid; i < CH * TN; i += 128) {
        const int tn = i & (TN - 1);
        const int c  = i >> 3;
        g_M[base + (size_t)c * NTOK + tn] =
            __float2bfloat16(buf0[tn * TOKP + (c >> 5) * 33 + (c & 31)]);
    }
}

// =====================================================================
extern "C" void kernel_launch(void* const* d_in, const int* in_sizes, int n_in,
                              void* d_out, int out_size)
{
    (void)in_sizes; (void)n_in; (void)out_size;
    const float* q  = (const float*)d_in[0];
    const float* k  = (const float*)d_in[1];
    const float* v  = (const float*)d_in[2];
    const float* Wq = (const float*)d_in[3];
    const float* Wk = (const float*)d_in[4];
    const float* Wv = (const float*)d_in[5];
    const float* Wp = (const float*)d_in[6];
    const float* bp = (const float*)d_in[7];
    float* out = (float*)d_out;

    __nv_bfloat16 *Qp, *Kp, *Vp, *Mp;
    cudaGetSymbolAddress((void**)&Qp, g_Q);
    cudaGetSymbolAddress((void**)&Kp, g_K);
    cudaGetSymbolAddress((void**)&Vp, g_V);
    cudaGetSymbolAddress((void**)&Mp, g_M);

    dim3 gg(NTOK / GBN, CH / GBM, BATCH);  // (32, 4, 8)
    gemm_bf16<float, __nv_bfloat16, true,  false><<<gg, 256>>>(Wq, q, Qp, nullptr);
    gemm_bf16<float, __nv_bfloat16, true,  false><<<gg, 256>>>(Wk, k, Kp, nullptr);
    gemm_bf16<float, __nv_bfloat16, false, false><<<gg, 256>>>(Wv, v, Vp, nullptr);
    ksum_kernel<<<BATCH * CH, 256>>>();
    mid_kernel<<<BATCH * (NTOK / TN), 128>>>();
    gemm_bf16<__nv_bfloat16, float, false, true><<<gg, 256>>>(Wp, Mp, out, bp);
}

// round 5
// speedup vs baseline: 2.1958x; 1.4340x over previous
#include <cuda_runtime.h>
#include <cuda_bf16.h>
#include <cstdint>
#include <cmath>

#define BATCH 8
#define CH    512
#define NTOK  4096

// ---------------- scratch (device globals) ----------------
__device__ __nv_bfloat16 g_Wt[4 * CH * CH];          // transposed bf16 weights [c][d]
__device__ __nv_bfloat16 g_X [3 * BATCH * CH * NTOK]; // bf16 q,k,v in [b][c][n]
__device__ __nv_bfloat16 g_Q [BATCH * CH * NTOK];
__device__ __nv_bfloat16 g_K [BATCH * CH * NTOK];
__device__ __nv_bfloat16 g_V [BATCH * CH * NTOK];
__device__ __nv_bfloat16 g_M [BATCH * CH * NTOK];
__device__ float g_Ksum[BATCH * CH];

// ---------------- helpers ----------------
__device__ __forceinline__ uint32_t smem_u32(const void* p) {
    uint32_t a;
    asm("{ .reg .u64 t; cvta.to.shared.u64 t, %1; cvt.u32.u64 %0, t; }" : "=r"(a) : "l"(p));
    return a;
}
__device__ __forceinline__ uint32_t bf2u(__nv_bfloat162 h) {
    union { __nv_bfloat162 h; uint32_t u; } z; z.h = h; return z.u;
}
__device__ __forceinline__ void mma_bf16(float c[4], const uint32_t a[4], const uint32_t b[2]) {
    asm volatile(
        "mma.sync.aligned.m16n8k16.row.col.f32.bf16.bf16.f32 "
        "{%0,%1,%2,%3}, {%4,%5,%6,%7}, {%8,%9}, {%0,%1,%2,%3};"
        : "+f"(c[0]), "+f"(c[1]), "+f"(c[2]), "+f"(c[3])
        : "r"(a[0]), "r"(a[1]), "r"(a[2]), "r"(a[3]), "r"(b[0]), "r"(b[1]));
}
__device__ __forceinline__ void ldsm_x4_t(uint32_t r[4], uint32_t addr) {
    asm volatile("ldmatrix.sync.aligned.m8n8.x4.trans.shared.b16 {%0,%1,%2,%3}, [%4];"
                 : "=r"(r[0]), "=r"(r[1]), "=r"(r[2]), "=r"(r[3]) : "r"(addr));
}
#define CP16(dst, src) \
    asm volatile("cp.async.cg.shared.global [%0], [%1], 16;" :: "r"(dst), "l"(src) : "memory")
#define CP_COMMIT() asm volatile("cp.async.commit_group;" ::: "memory")
#define CP_WAIT(n)  asm volatile("cp.async.wait_group %0;" :: "n"(n) : "memory")

// =====================================================================
// weight prep: W fp32 [d][c] -> bf16 [c][d]   (grid 16,16,4)
// =====================================================================
__global__ __launch_bounds__(256) void wprep(
    const float* __restrict__ W0, const float* __restrict__ W1,
    const float* __restrict__ W2, const float* __restrict__ W3,
    __nv_bfloat16* __restrict__ D)
{
    __shared__ float t[32][33];
    const int z = blockIdx.z;
    const float* S = (z == 0) ? W0 : (z == 1) ? W1 : (z == 2) ? W2 : W3;
    __nv_bfloat16* Dz = D + (size_t)z * CH * CH;
    const int d0 = blockIdx.x * 32, c0 = blockIdx.y * 32;
    const int x = threadIdx.x & 31, y = threadIdx.x >> 5;
#pragma unroll
    for (int i = 0; i < 4; i++)
        t[y + 8 * i][x] = S[(size_t)(d0 + y + 8 * i) * CH + c0 + x];
    __syncthreads();
    const int m2 = threadIdx.x & 15, r0 = threadIdx.x >> 4;
#pragma unroll
    for (int i = 0; i < 2; i++) {
        const int r = r0 + 16 * i;
        __nv_bfloat162 h = __float22bfloat162_rn(make_float2(t[m2 * 2][r], t[m2 * 2 + 1][r]));
        *(__nv_bfloat162*)&Dz[(size_t)(c0 + r) * CH + d0 + m2 * 2] = h;
    }
}

// =====================================================================
// input prep: fp32 -> bf16 elementwise (grid 8192,1,3)
// =====================================================================
__global__ __launch_bounds__(256) void xconv(
    const float4* __restrict__ s0, const float4* __restrict__ s1,
    const float4* __restrict__ s2, uint4* __restrict__ d)
{
    const int z = blockIdx.z;
    const float4* s = (z == 0) ? s0 : (z == 1) ? s1 : s2;
    uint4* dz = d + (size_t)z * (BATCH * CH * NTOK / 8);
    const size_t i = (size_t)blockIdx.x * 256 + threadIdx.x;
    float4 a = s[2 * i], b = s[2 * i + 1];
    uint4 o;
    o.x = bf2u(__float22bfloat162_rn(make_float2(a.x, a.y)));
    o.y = bf2u(__float22bfloat162_rn(make_float2(a.z, a.w)));
    o.z = bf2u(__float22bfloat162_rn(make_float2(b.x, b.y)));
    o.w = bf2u(__float22bfloat162_rn(make_float2(b.z, b.w)));
    dz[i] = o;
}

// =====================================================================
// GEMM: C[b,d,n] = sum_c At[c,d] * B[b,c,n]  (+elu+1 | +bias)
// At bf16 [512,512] (c-major rows, d contiguous), B bf16 [8][512][4096].
// BM=BN=128, BK=32, 4-stage cp.async, 256 thr, 8 warps (4m x 2n), 32x64.
// Smem tiles [k][m]/[k][n]: 32 rows x 256B, 16B chunks swizzled ^ (k&7).
// =====================================================================
#define STG_SZ 16384
#define GEMM_SMEM (4 * STG_SZ)

template<bool PROJ, typename OutT, bool BIAS>
__global__ __launch_bounds__(256, 2) void gemm_ca(
    const __nv_bfloat16* __restrict__ A0, const __nv_bfloat16* __restrict__ A1,
    const __nv_bfloat16* __restrict__ A2,
    const __nv_bfloat16* __restrict__ X0, const __nv_bfloat16* __restrict__ X1,
    const __nv_bfloat16* __restrict__ X2,
    void* C0, void* C1, void* C2, const float* __restrict__ bias)
{
    extern __shared__ char smem[];
    const uint32_t sb = smem_u32(smem);

    int b; bool elu;
    const __nv_bfloat16 *A, *B; OutT* C;
    if (PROJ) {
        const int which = blockIdx.z >> 3; b = blockIdx.z & 7;
        A = (which == 0) ? A0 : (which == 1) ? A1 : A2;
        B = (which == 0) ? X0 : (which == 1) ? X1 : X2;
        C = (OutT*)((which == 0) ? C0 : (which == 1) ? C1 : C2);
        elu = (which < 2);
    } else {
        b = blockIdx.z; A = A0; B = X0; C = (OutT*)C0; elu = false;
    }

    const int m0 = blockIdx.y * 128, n0 = blockIdx.x * 128;
    const __nv_bfloat16* Bb = B + (size_t)b * CH * NTOK;
    OutT* Cb = C + (size_t)b * CH * NTOK;

    const int tid = threadIdx.x;
    const int lane = tid & 31, wid = tid >> 5;
    const int wm = wid & 3, wn = wid >> 2;
    const int gr = lane >> 2, kc = lane & 3;

    // cp.async mapping: row = tid>>3 (0..31), chunks 2*(tid&7), +1
    const int lr = tid >> 3;
    const int lc = (tid & 7) * 2;
    const int swz = lr & 7;

    // ldmatrix lane mapping
    const int klow = ((lane >> 3) & 1) * 8 + (lane & 7);
    const int cg   = lane >> 4;

    float acc[2][8][4];
#pragma unroll
    for (int i = 0; i < 2; i++)
#pragma unroll
        for (int j = 0; j < 8; j++)
#pragma unroll
            for (int r = 0; r < 4; r++) acc[i][j][r] = 0.f;

    auto issue = [&](int kt, int s) {
        const __nv_bfloat16* pa = A  + (size_t)(kt * 32 + lr) * CH   + m0 + lc * 8;
        const __nv_bfloat16* pb = Bb + (size_t)(kt * 32 + lr) * NTOK + n0 + lc * 8;
        const uint32_t base = sb + s * STG_SZ + lr * 256;
        CP16(base + ((lc     ^ swz) * 16),        pa);
        CP16(base + (((lc+1) ^ swz) * 16),        pa + 8);
        CP16(base + ((lc     ^ swz) * 16) + 8192, pb);
        CP16(base + (((lc+1) ^ swz) * 16) + 8192, pb + 8);
    };

#pragma unroll
    for (int s = 0; s < 3; s++) { issue(s, s); CP_COMMIT(); }

    const int KT = CH / 32;  // 16
#pragma unroll 1
    for (int kt = 0; kt < KT; ++kt) {
        CP_WAIT(2);
        __syncthreads();
        const int s = kt & 3;
        const uint32_t stA = sb + s * STG_SZ;

#pragma unroll
        for (int ks = 0; ks < 2; ++ks) {
            const int krow = ks * 16 + klow;
            const int kx = krow & 7;
            const uint32_t rb = stA + krow * 256;

            uint32_t af[2][4];
#pragma unroll
            for (int i = 0; i < 2; i++) {
                const int mc = wm * 4 + i * 2 + cg;
                uint32_t r[4];
                ldsm_x4_t(r, rb + ((mc ^ kx) * 16));
                af[i][0] = r[0]; af[i][1] = r[2]; af[i][2] = r[1]; af[i][3] = r[3];
            }
            uint32_t bf[8][2];
#pragma unroll
            for (int jj = 0; jj < 4; jj++) {
                const int nc = wn * 8 + jj * 2 + cg;
                uint32_t r[4];
                ldsm_x4_t(r, rb + 8192 + ((nc ^ kx) * 16));
                bf[jj * 2][0]     = r[0];
                bf[jj * 2][1]     = r[1];
                bf[jj * 2 + 1][0] = r[2];
                bf[jj * 2 + 1][1] = r[3];
            }
#pragma unroll
            for (int i = 0; i < 2; i++)
#pragma unroll
                for (int j = 0; j < 8; j++)
                    mma_bf16(acc[i][j], af[i], bf[j]);
        }

        if (kt + 3 < KT) issue(kt + 3, (kt + 3) & 3);
        CP_COMMIT();
    }

    // epilogue
#pragma unroll
    for (int i = 0; i < 2; i++) {
        const int row = m0 + wm * 32 + i * 16 + gr;
        const float bi0 = BIAS ? bias[row] : 0.f;
        const float bi1 = BIAS ? bias[row + 8] : 0.f;
#pragma unroll
        for (int j = 0; j < 8; j++) {
            const int col = n0 + wn * 64 + j * 8 + kc * 2;
            float c0 = acc[i][j][0], c1 = acc[i][j][1];
            float c2 = acc[i][j][2], c3 = acc[i][j][3];
            if (PROJ && elu) {
                c0 = (c0 > 0.f) ? (c0 + 1.f) : __expf(c0);
                c1 = (c1 > 0.f) ? (c1 + 1.f) : __expf(c1);
                c2 = (c2 > 0.f) ? (c2 + 1.f) : __expf(c2);
                c3 = (c3 > 0.f) ? (c3 + 1.f) : __expf(c3);
            }
            if (BIAS) { c0 += bi0; c1 += bi0; c2 += bi1; c3 += bi1; }
            if constexpr (sizeof(OutT) == 2) {
                *(__nv_bfloat162*)&Cb[(size_t)row * NTOK + col] =
                    __float22bfloat162_rn(make_float2(c0, c1));
                *(__nv_bfloat162*)&Cb[(size_t)(row + 8) * NTOK + col] =
                    __float22bfloat162_rn(make_float2(c2, c3));
            } else {
                *(float2*)&Cb[(size_t)row * NTOK + col]       = make_float2(c0, c1);
                *(float2*)&Cb[(size_t)(row + 8) * NTOK + col] = make_float2(c2, c3);
            }
        }
    }
}

// =====================================================================
// Ksum[b,c] = sum_n K[b,c,n]
// =====================================================================
__global__ __launch_bounds__(256) void ksum_kernel()
{
    const int row = blockIdx.x;
    const __nv_bfloat16* p = g_K + (size_t)row * NTOK;
    const int i = threadIdx.x * 16;
    uint4 u0 = *(const uint4*)(p + i);
    uint4 u1 = *(const uint4*)(p + i + 8);
    float s = 0.f;
    const __nv_bfloat162* h0 = (const __nv_bfloat162*)&u0;
    const __nv_bfloat162* h1 = (const __nv_bfloat162*)&u1;
#pragma unroll
    for (int j = 0; j < 4; j++) {
        float2 f0 = __bfloat1622float2(h0[j]);
        float2 f1 = __bfloat1622float2(h1[j]);
        s += f0.x + f0.y + f1.x + f1.y;
    }
#pragma unroll
    for (int o = 16; o > 0; o >>= 1) s += __shfl_xor_sync(0xffffffffu, s, o);
    __shared__ float red[8];
    if ((threadIdx.x & 31) == 0) red[threadIdx.x >> 5] = s;
    __syncthreads();
    if (threadIdx.x == 0) {
        float t = 0.f;
#pragma unroll
        for (int w = 0; w < 8; w++) t += red[w];
        g_Ksum[row] = t;
    }
}

// =====================================================================
// Middle stage: per token S=QK^T, Z=1/(Q.Ksum+eps), O=diag(Z) S V -> g_M [c][n]
// TN=16 tokens/block, 256 threads.
// =====================================================================
#define TN    16
#define TOKP  529
#define SSTR  273
#define MID_SMEM ((2 * TN * TOKP + TN * SSTR + TN * 17 + 16 * 33) * 4)

__global__ __launch_bounds__(256) void mid_kernel()
{
    extern __shared__ float sm[];
    float* buf0 = sm;
    float* buf1 = buf0 + TN * TOKP;
    float* Ss   = buf1 + TN * TOKP;
    float* Zs   = Ss + TN * SSTR;
    float* Ksm  = Zs + TN * 17;

    const int blk = blockIdx.x;
    const int b   = blk >> 8;
    const int n0  = (blk & 255) * TN;
    const size_t base = (size_t)b * CH * NTOK + n0;
    const int tid = threadIdx.x;

    for (int i = tid; i < CH; i += 256)
        Ksm[(i >> 5) * 33 + (i & 31)] = g_Ksum[b * CH + i];

    for (int i = tid; i < CH * TN; i += 256) {
        const int tn = i & (TN - 1);
        const int c  = i >> 4;
        const int off = tn * TOKP + (c >> 5) * 33 + (c & 31);
        buf0[off] = __bfloat162float(g_K[base + (size_t)c * NTOK + tn]);
        buf1[off] = __bfloat162float(g_Q[base + (size_t)c * NTOK + tn]);
    }
    __syncthreads();

    const int w    = tid >> 5;
    const int lane = tid & 31;
    const int hp   = lane & 15;
    const int half = lane >> 4;

#pragma unroll
    for (int tt = 0; tt < 2; ++tt) {
        const int t = w * 2 + tt;
        const float* Kt = &buf0[t * TOKP];
        const float* Qt = &buf1[t * TOKP];
        float kcol[32];
#pragma unroll
        for (int d = 0; d < 32; d++) kcol[d] = Kt[hp * 33 + d];
#pragma unroll
        for (int hi = 0; hi < 8; hi++) {
            const int h = half * 8 + hi;
            float s = 0.f;
#pragma unroll
            for (int d = 0; d < 32; d++) s = fmaf(Qt[h * 33 + d], kcol[d], s);
            Ss[t * SSTR + h * 17 + hp] = s;
        }
        if (half == 0) {
            float dn = 0.f;
#pragma unroll
            for (int d = 0; d < 32; d++) dn = fmaf(Qt[hp * 33 + d], Ksm[hp * 33 + d], dn);
            Zs[t * 17 + hp] = 1.f / (dn + 1e-5f);
        }
    }
    __syncthreads();

    for (int i = tid; i < CH * TN; i += 256) {
        const int tn = i & (TN - 1);
        const int c  = i >> 4;
        buf1[tn * TOKP + (c >> 5) * 33 + (c & 31)] =
            __bfloat162float(g_V[base + (size_t)c * NTOK + tn]);
    }
    __syncthreads();

#pragma unroll
    for (int tt = 0; tt < 2; ++tt) {
        const int t = w * 2 + tt;
        const float* Vt = &buf1[t * TOKP];
        float vcol[16];
#pragma unroll
        for (int h = 0; h < 16; h++) vcol[h] = Vt[h * 33 + lane];
#pragma unroll
        for (int h = 0; h < 16; h++) {
            float a = 0.f;
#pragma unroll
            for (int q = 0; q < 16; q++) a = fmaf(Ss[t * SSTR + h * 17 + q], vcol[q], a);
            buf0[t * TOKP + h * 33 + lane] = a * Zs[t * 17 + h];
        }
    }
    __syncthreads();

    // write g_M [c][n]
    for (int i = tid; i < CH * TN; i += 256) {
        const int tn = i & (TN - 1);
        const int c  = i >> 4;
        g_M[base + (size_t)c * NTOK + tn] =
            __float2bfloat16(buf0[tn * TOKP + (c >> 5) * 33 + (c & 31)]);
    }
}

// =====================================================================
extern "C" void kernel_launch(void* const* d_in, const int* in_sizes, int n_in,
                              void* d_out, int out_size)
{
    (void)in_sizes; (void)n_in; (void)out_size;
    const float* q  = (const float*)d_in[0];
    const float* k  = (const float*)d_in[1];
    const float* v  = (const float*)d_in[2];
    const float* Wq = (const float*)d_in[3];
    const float* Wk = (const float*)d_in[4];
    const float* Wv = (const float*)d_in[5];
    const float* Wp = (const float*)d_in[6];
    const float* bp = (const float*)d_in[7];
    float* out = (float*)d_out;

    void *wt, *x, *Qp, *Kp, *Vp, *Mp;
    cudaGetSymbolAddress(&wt, g_Wt);
    cudaGetSymbolAddress(&x,  g_X);
    cudaGetSymbolAddress(&Qp, g_Q);
    cudaGetSymbolAddress(&Kp, g_K);
    cudaGetSymbolAddress(&Vp, g_V);
    cudaGetSymbolAddress(&Mp, g_M);
    __nv_bfloat16* Wt = (__nv_bfloat16*)wt;
    __nv_bfloat16* X  = (__nv_bfloat16*)x;
    const size_t XS = (size_t)BATCH * CH * NTOK;

    cudaFuncSetAttribute(gemm_ca<true,  __nv_bfloat16, false>,
                         cudaFuncAttributeMaxDynamicSharedMemorySize, GEMM_SMEM);
    cudaFuncSetAttribute(gemm_ca<false, float, true>,
                         cudaFuncAttributeMaxDynamicSharedMemorySize, GEMM_SMEM);
    cudaFuncSetAttribute(mid_kernel,
                         cudaFuncAttributeMaxDynamicSharedMemorySize, MID_SMEM);

    // 1. prep
    wprep<<<dim3(16, 16, 4), 256>>>(Wq, Wk, Wv, Wp, Wt);
    xconv<<<dim3(8192, 1, 3), 256>>>((const float4*)q, (const float4*)k,
                                     (const float4*)v, (uint4*)X);

    // 2. projections (fused 3-in-1)
    dim3 gp(NTOK / 128, CH / 128, 3 * BATCH);
    gemm_ca<true, __nv_bfloat16, false><<<gp, 256, GEMM_SMEM>>>(
        Wt, Wt + CH * CH, Wt + 2 * CH * CH,
        X, X + XS, X + 2 * XS,
        Qp, Kp, Vp, nullptr);

    // 3. Ksum + middle
    ksum_kernel<<<BATCH * CH, 256>>>();
    mid_kernel<<<BATCH * (NTOK / TN), 256, MID_SMEM>>>();

    // 4. output projection
    dim3 gf(NTOK / 128, CH / 128, BATCH);
    gemm_ca<false, float, true><<<gf, 256, GEMM_SMEM>>>(
        Wt + 3 * CH * CH, nullptr, nullptr,
        (__nv_bfloat16*)Mp, nullptr, nullptr,
        out, nullptr, nullptr, bp);
}